// round 17
// baseline (speedup 1.0000x reference)
#include <cuda_runtime.h>
#include <cuda_bf16.h>
#include <cstdint>

#define H        4096
#define NSTEPS   100
#define IN_DIM   512
#define OUT_DIM  64
#define ND       10
#define NBLK     128          // persistent blocks; block owns 32 cols + 32 neurons
#define TPB      1024
#define UWCAP    20           // max d==1 columns per (row, block); P(overflow)~1e-7
#define DECAY_F  0.9512294245007141f

// ---------------- static device state ----------------------------------------
__device__ float          g_IIN[NSTEPS * H];            // input currents (1.6 MB)
__device__ unsigned char  g_DPK[(size_t)H * H];         // byte delays 1..9 (16 MB)
__device__ unsigned       g_UM[H * NBLK];               // d==1 column masks (2 MB)
__device__ float          g_UW[(size_t)H * NBLK * UWCAP]; // compact d==1 weights (42 MB)
__device__ unsigned       g_mask[2][NBLK];              // parity-buffered spike ballots
__device__ float          g_vsum[H];
__device__ int            g_arr[NBLK];                  // barrier arrivals (epoch)
__device__ int            g_rel;                        // barrier release (epoch)
__device__ unsigned       g_barA = 0u;                  // atomic barrier (2 uses)
__device__ unsigned       g_barG = 0u;

// ---------------- atomic grid barrier (prologue/epilogue only) ----------------
__device__ __forceinline__ void grid_sync() {
    __syncthreads();
    if (threadIdx.x == 0) {
        __threadfence();
        unsigned gen = *((volatile unsigned*)&g_barG);
        unsigned a = atomicAdd(&g_barA, 1u);
        if (a == NBLK - 1u) {
            g_barA = 0u;
            __threadfence();
            atomicAdd(&g_barG, 1u);
        } else {
            while (*((volatile unsigned*)&g_barG) == gen) { }
        }
        __threadfence();
    }
    __syncthreads();
}

// ---------------- single fused persistent kernel ------------------------------
__global__ void __launch_bounds__(TPB, 1) reservoir_kernel(
    const float* __restrict__ x,      // [100,512]
    const float* __restrict__ win,    // [512,4096]
    const float* __restrict__ W,      // [4096,4096]
    const float* __restrict__ Rw,     // [4096,64]
    const float* __restrict__ Rb,     // [64]
    const int*   __restrict__ delays, // [4096,4096]
    float* __restrict__ out)          // [64]
{
    __shared__ float          s_acc[8 * 32 * 32];  // 32 KB lazy slices d=2..9
    __shared__ float          s_urg[32 * 32];      // 4 KB urgent warp partials
    __shared__ unsigned short s_dense[H];          // 8 KB dense spike list
    __shared__ float          s_ring[ND][32];      // block-local delay ring
    __shared__ int            s_ns;

    const int tid  = threadIdx.x;
    const int b    = blockIdx.x;
    const int lane = tid & 31;
    const int wrp  = tid >> 5;
    const int col0 = b << 5;
    const float*         Wb = W + col0 + lane;
    const unsigned char* Db = g_DPK + col0 + lane;

    // ---------------- prologue ----------------
    if (b < 40) {                          // input GEMM: 10 steps x 1024 cols
        float* xs = s_acc;
        int t0 = (b >> 2) * 10;
        int j  = ((b & 3) << 10) + tid;
        for (int idx = tid; idx < 10 * IN_DIM; idx += TPB)
            xs[idx] = x[t0 * IN_DIM + idx];
        __syncthreads();
        float a[10];
#pragma unroll
        for (int tt = 0; tt < 10; tt++) a[tt] = 0.f;
        for (int k = 0; k < IN_DIM; k++) {
            float wv = __ldg(&win[k * H + j]);
#pragma unroll
            for (int tt = 0; tt < 10; tt++) a[tt] += xs[tt * IN_DIM + k] * wv;
        }
#pragma unroll
        for (int tt = 0; tt < 10; tt++) g_IIN[(t0 + tt) * H + j] = a[tt];
        __syncthreads();
    } else {                               // pack delays int32 -> u8
        const int4* dl = (const int4*)delays;
        uchar4* dp = (uchar4*)g_DPK;
        for (int idx = (b - 40) * TPB + tid; idx < H * H / 4; idx += 88 * TPB) {
            int4 d4 = dl[idx];
            dp[idx] = make_uchar4((unsigned char)d4.x, (unsigned char)d4.y,
                                  (unsigned char)d4.z, (unsigned char)d4.w);
        }
    }
    // build urgent (d==1) masks + compact weights: 4 cells per thread
    {
        int gtid = b * TPB + tid;
        for (int c = gtid * 4; c < gtid * 4 + 4; c++) {
            int i  = c >> 7;               // row
            int bb = c & 127;              // target block
            const int*   drow = delays + i * H + (bb << 5);
            const float* wrow = W + i * H + (bb << 5);
            unsigned msk = 0; int cnt = 0;
            int base = c * UWCAP;
            for (int cc = 0; cc < 32; cc++) {
                int dv = __ldg(drow + cc);
                if (dv == 1) {
                    msk |= 1u << cc;
                    if (cnt < UWCAP) g_UW[base + cnt] = __ldg(wrow + cc);
                    cnt++;
                }
            }
            g_UM[c] = msk;
        }
    }
    if (tid < ND * 32) ((float*)s_ring)[tid] = 0.f;
    if (tid == 0) {                        // replay-safe barrier reset
        *((volatile int*)&g_arr[b]) = 0;
        if (b == 0) *((volatile int*)&g_rel) = 0;
    }

    float v = 0.f, gam = 1.f, rate = 0.f, vsum = 0.f;

    // LIF + publish mask(t) + arrive(epoch t+1); block0 aggregates + releases
    auto lif_publish = [&](int t, float iin, float irec) {
        float itot = __fmul_rn(__fadd_rn(iin, irec), gam);
        v = __fadd_rn(__fmul_rn(v, DECAY_F), itot);
        bool sp = (v >= 1.0f);
        if (sp) v = 0.f;
        float spf = sp ? 1.f : 0.f;
        rate = __fadd_rn(__fmul_rn(0.9f, rate), __fmul_rn(0.1f, spf));
        gam  = __fadd_rn(gam, __fmul_rn(0.01f, __fadd_rn(0.1f, -rate)));
        gam  = fminf(fmaxf(gam, 0.5f), 2.0f);
        vsum += v;
        unsigned m = __ballot_sync(0xffffffffu, sp);
        if (lane == 0) {
            __stcg(&g_mask[t & 1][b], m);
            __threadfence();                           // mask before arrival
            *((volatile int*)&g_arr[b]) = t + 1;
        }
        if (b == 0) {                                  // aggregate + release
            const volatile int* va = (const volatile int*)g_arr;
            for (;;) {
                int m0 = va[lane], m1 = va[lane + 32];
                int m2 = va[lane + 64], m3 = va[lane + 96];
                int mn = min(min(m0, m1), min(m2, m3));
                if (__ballot_sync(0xffffffffu, mn >= t + 1) == 0xffffffffu) break;
            }
            __threadfence();
            if (lane == 0) *((volatile int*)&g_rel) = t + 1;
        }
    };

    grid_sync();                           // prologue data + resets visible
    if (wrp == 0)                          // step 0: ring empty
        lif_publish(0, __ldcg(&g_IIN[col0 + lane]), 0.f);

    for (int t = 0; t < NSTEPS - 1; t++) {
        const int par = t & 1;

        float iin_next = 0.f;
        if (wrp == 0) iin_next = __ldcg(&g_IIN[(t + 1) * H + col0 + lane]);

        if (wrp == 0) {
            // ---- poll release(epoch t+1) = all masks(t) published ----
            for (;;) {
                int r = *((volatile int*)&g_rel);
                if (__ballot_sync(0xffffffffu, r >= t + 1) == 0xffffffffu) break;
            }
            __threadfence();                            // acquire
            // ---- decode 128 ballots -> dense spike list ----
            uint4 mw = __ldcg(&((const uint4*)g_mask[par])[lane]);
            int c0 = __popc(mw.x), c1 = __popc(mw.y);
            int c2 = __popc(mw.z), c3 = __popc(mw.w);
            int ssum = c0 + c1 + c2 + c3;
            int inc = ssum;
#pragma unroll
            for (int o = 1; o < 32; o <<= 1) {
                int nv = __shfl_up_sync(0xffffffffu, inc, o);
                if (lane >= o) inc += nv;
            }
            int off = inc - ssum;
            int nb  = lane << 7;
            unsigned mm;
            mm = mw.x; while (mm) { int bi = __ffs(mm) - 1; mm &= mm - 1;
                s_dense[off++] = (unsigned short)(nb + bi); }
            mm = mw.y; while (mm) { int bi = __ffs(mm) - 1; mm &= mm - 1;
                s_dense[off++] = (unsigned short)(nb + 32 + bi); }
            mm = mw.z; while (mm) { int bi = __ffs(mm) - 1; mm &= mm - 1;
                s_dense[off++] = (unsigned short)(nb + 64 + bi); }
            mm = mw.w; while (mm) { int bi = __ffs(mm) - 1; mm &= mm - 1;
                s_dense[off++] = (unsigned short)(nb + 96 + bi); }
            if (lane == 31) s_ns = inc;
        } else {
            // ---- warps 1-31: zero lazy accumulators ----
            for (int i = tid - 32; i < 8 * 32 * 32; i += TPB - 32) s_acc[i] = 0.f;
        }
        __syncthreads();

        // ================= URGENT: d==1 contributions (critical path) ========
        const int ns = s_ns;
        {
            const unsigned lb = 1u << lane, below = lb - 1u;
            float accu = 0.f;
            int k = wrp;
            for (; k + 96 < ns; k += 128) {
                int cc0 = (((int)s_dense[k])      << 7) + b;
                int cc1 = (((int)s_dense[k + 32]) << 7) + b;
                int cc2 = (((int)s_dense[k + 64]) << 7) + b;
                int cc3 = (((int)s_dense[k + 96]) << 7) + b;
                unsigned m0 = __ldcg(&g_UM[cc0]);
                unsigned m1 = __ldcg(&g_UM[cc1]);
                unsigned m2 = __ldcg(&g_UM[cc2]);
                unsigned m3 = __ldcg(&g_UM[cc3]);
                if (m0 & lb) accu += __ldcg(&g_UW[cc0 * UWCAP + __popc(m0 & below)]);
                if (m1 & lb) accu += __ldcg(&g_UW[cc1 * UWCAP + __popc(m1 & below)]);
                if (m2 & lb) accu += __ldcg(&g_UW[cc2 * UWCAP + __popc(m2 & below)]);
                if (m3 & lb) accu += __ldcg(&g_UW[cc3 * UWCAP + __popc(m3 & below)]);
            }
            for (; k < ns; k += 32) {
                int cc0 = (((int)s_dense[k]) << 7) + b;
                unsigned m0 = __ldcg(&g_UM[cc0]);
                if (m0 & lb) accu += __ldcg(&g_UW[cc0 * UWCAP + __popc(m0 & below)]);
            }
            s_urg[(lane << 5) + (wrp ^ lane)] = accu;   // unique slot per (w,l)
        }
        __syncthreads();

        // ---- warp 0: urgent reduce -> LIF(t+1) -> publish + arrive ----------
        if (wrp == 0) {
            float su = 0.f;
            const float* ub = &s_urg[lane << 5];
#pragma unroll
            for (int ww = 0; ww < 32; ww++) su += ub[ww ^ lane];
            int slot1 = (t + 1) % ND;
            float irec = s_ring[slot1][lane] + su;      // same order as R16
            s_ring[slot1][lane] = 0.f;
            lif_publish(t + 1, iin_next, irec);
        }
        // warps 1-31 fall straight into lazy; w0 joins after publish/aggregate

        // ================= LAZY: d>=2 scatter (overlaps barrier) =============
        {
            const int swz = (lane << 5) + (wrp ^ lane);
            int k = wrp;
            for (; k + 96 < ns; k += 128) {
                int i0 = s_dense[k],      i1 = s_dense[k + 32];
                int i2 = s_dense[k + 64], i3 = s_dense[k + 96];
                float w0 = __ldcg(Wb + (i0 << 12));
                float w1 = __ldcg(Wb + (i1 << 12));
                float w2 = __ldcg(Wb + (i2 << 12));
                float w3 = __ldcg(Wb + (i3 << 12));
                int d0 = (int)__ldg(Db + (i0 << 12));
                int d1 = (int)__ldg(Db + (i1 << 12));
                int d2 = (int)__ldg(Db + (i2 << 12));
                int d3 = (int)__ldg(Db + (i3 << 12));
                if (d0 >= 2) s_acc[((d0 - 2) << 10) + swz] += w0;
                if (d1 >= 2) s_acc[((d1 - 2) << 10) + swz] += w1;
                if (d2 >= 2) s_acc[((d2 - 2) << 10) + swz] += w2;
                if (d3 >= 2) s_acc[((d3 - 2) << 10) + swz] += w3;
            }
            for (; k < ns; k += 32) {
                int i0 = s_dense[k];
                float w0 = __ldcg(Wb + (i0 << 12));
                int d0 = (int)__ldg(Db + (i0 << 12));
                if (d0 >= 2) s_acc[((d0 - 2) << 10) + swz] += w0;
            }
        }
        __syncthreads();

        // ---- lazy reduce: 8 slices -> ring slots t+2..t+9 -------------------
        if (tid < 256) {
            int d = tid >> 5, l2 = tid & 31;            // slice d -> delay d+2
            const float* base2 = &s_acc[(d << 10) + (l2 << 5)];
            float s = 0.f;
#pragma unroll
            for (int ww = 0; ww < 32; ww++) s += base2[ww ^ l2];
            int s2 = (t % ND) + d + 2;                  // max 18 -> one wrap
            if (s2 >= ND) s2 -= ND;
            s_ring[s2][l2] += s;
        }
        __syncthreads();                                // reduce before re-zero
    }

    // ---------------- epilogue: readout ----------------
    if (wrp == 0) __stcg(&g_vsum[col0 + lane], vsum);
    grid_sync();

    if (b == 0) {
        float* s_red = s_acc;
        int o = tid & 63, q = tid >> 6;                 // 16 partials per output
        float s = 0.f;
        for (int jj = q * 256; jj < q * 256 + 256; jj++) {
            float vm = __ldcg(&g_vsum[jj]) / 100.0f;
            s += vm * __ldg(&Rw[jj * OUT_DIM + o]);
        }
        s_red[tid] = s;
        __syncthreads();
        if (tid < OUT_DIM) {
            float tot = 0.f;
#pragma unroll
            for (int q2 = 0; q2 < 16; q2++) tot += s_red[q2 * 64 + tid];
            out[tid] = tot + __ldg(&Rb[tid]);
        }
    }
}

// ---------------- host launch: ONE kernel -------------------------------------
extern "C" void kernel_launch(void* const* d_in, const int* in_sizes, int n_in,
                              void* d_out, int out_size) {
    const float* x      = (const float*)d_in[0];
    const float* win    = (const float*)d_in[1];
    const float* W      = (const float*)d_in[2];
    const float* Rw     = (const float*)d_in[3];
    const float* Rb     = (const float*)d_in[4];
    const int*   delays = (const int*)d_in[5];
    (void)in_sizes; (void)n_in; (void)out_size;

    reservoir_kernel<<<NBLK, TPB>>>(x, win, W, Rw, Rb, delays, (float*)d_out);
}